// round 17
// baseline (speedup 1.0000x reference)
#include <cuda_runtime.h>
#include <cuda_fp16.h>
#include <cstdint>

// ---------------------------------------------------------------- problem
#define BATCH  8192
#define IN_F   1024
#define OUT_F  1024
#define NB     11
#define BKF    8                    // features per chunk
#define NITER  (IN_F / BKF)         // 128 chunks total
#define KSPLIT 2
#define NQ     (NITER / KSPLIT)     // 64 chunks per K-half
#define BM     128
#define BN     128
#define THREADS 256
#define NSTEP  4                    // k32 steps per chunk (2 features each)

// smem (u32 words)
// A stored (compressed): 8 halves/feature -> 32 words/row/chunk, stride 36
// B dense: 16 halves/feature -> 64 words/row/chunk, stride 68
// meta: [128][4] u32 per buffer; word s of a row = [feat 2s (k0-15) | feat 2s+1 (k16-31)]
#define SKA    36
#define SKB    68
#define A_TB   (128 * SKA)          // 4608 words
#define B_TB   (128 * SKB)          // 8704 words
#define M_TB   (128 * 4)            // 512 words
#define AS_OFF 0
#define BS_OFF (2 * A_TB)           // 9216
#define ME_OFF (BS_OFF + 2 * B_TB)  // 26624
#define SMEM_BYTES ((ME_OFF + 2 * M_TB) * 4)   // 110592 B -> 2 CTAs/SM

// fused prep grid split
#define PREP_WH_BLOCKS (OUT_F * IN_F / 256)            // 4096
#define PREP_TR_BLOCKS ((IN_F / 32) * (BATCH / 32))    // 8192

// ---------------------------------------------------------------- scratch
__device__ uint32_t g_Wh[(size_t)OUT_F * IN_F * 8];         // 16 halves per (o,i), sparse slot order
__device__ float    g_xT[(size_t)IN_F * BATCH];             // x transposed [i][b]
__device__ float    g_part[(size_t)KSPLIT * BATCH * OUT_F]; // split-K partials (64MB)

// ---------------------------------------------------------------- helpers
__device__ __forceinline__ uint32_t smem_u32(const void* p) {
    uint32_t a;
    asm("{ .reg .u64 t; cvta.to.shared.u64 t, %1; cvt.u32.u64 %0, t; }" : "=r"(a) : "l"(p));
    return a;
}
#define CP_ASYNC16(d, s) asm volatile("cp.async.cg.shared.global [%0], [%1], 16;" :: "r"(d), "l"(s) : "memory")
#define CP_COMMIT()      asm volatile("cp.async.commit_group;" ::: "memory")
#define CP_WAIT0()       asm volatile("cp.async.wait_group 0;" ::: "memory")

#define LDSM_X4(r0, r1, r2, r3, addr)                                         \
    asm volatile("ldmatrix.sync.aligned.m8n8.x4.shared.b16 {%0,%1,%2,%3}, [%4];" \
                 : "=r"(r0), "=r"(r1), "=r"(r2), "=r"(r3) : "r"(addr))

// sparse m16n8k32 f16 mma, ordered metadata, selector 0
#define MMA_SP(d, a, b, e)                                                    \
    asm volatile(                                                             \
        "mma.sp::ordered_metadata.sync.aligned.m16n8k32.row.col.f32.f16.f16.f32 " \
        "{%0,%1,%2,%3}, {%4,%5,%6,%7}, {%8,%9,%10,%11}, {%0,%1,%2,%3}, %12, 0x0;\n" \
        : "+f"((d)[0]), "+f"((d)[1]), "+f"((d)[2]), "+f"((d)[3])              \
        : "r"((a)[0]), "r"((a)[1]), "r"((a)[2]), "r"((a)[3]),                 \
          "r"((b)[0]), "r"((b)[1]), "r"((b)[2]), "r"((b)[3]), "r"(e))

// streaming (evict-first) 8B store / 16B load for single-use partials
__device__ __forceinline__ void stcs8(float* p, float a, float b) {
    asm volatile("st.global.cs.v2.f32 [%0], {%1, %2};" :: "l"(p), "f"(a), "f"(b) : "memory");
}
__device__ __forceinline__ float4 ldcs16(const float* p) {
    float4 v;
    asm volatile("ld.global.cs.v4.f32 {%0,%1,%2,%3}, [%4];"
                 : "=f"(v.x), "=f"(v.y), "=f"(v.z), "=f"(v.w) : "l"(p));
    return v;
}

__device__ __forceinline__ uint32_t packh2(float lo, float hi) {
    __half2 h = __floats2half2_rn(lo, hi);
    return *(uint32_t*)&h;
}

// single cubic B-spline basis at center index kf (float)
__device__ __forceinline__ float basis1(float x, float kf) {
    float u  = fabsf(x - (-1.25f + 0.25f * kf)) * 4.0f;
    float c2 = 2.0f - u;
    float c1 = 1.0f - u;
    float c23 = c2 * c2 * c2;
    float inner = (c23 - 4.0f * c1 * c1 * c1) * (1.0f / 6.0f);
    float outer = c23 * (1.0f / 6.0f);
    return (u < 1.0f) ? inner : ((u < 2.0f) ? outer : 0.0f);
}

// ---------------------------------------------------------------- fused prep
// weights packed in sparse slot order:
// [sw0,sw2,sw4,sw6 | sw8,sw10,0,0 | sw1,sw3,sw5,sw7 | sw9,bw,0,0]
__global__ void prep_fused_kernel(const float* __restrict__ bw,
                                  const float* __restrict__ sw,
                                  const float* __restrict__ x) {
    if (blockIdx.x < PREP_WH_BLOCKS) {
        int idx = blockIdx.x * 256 + threadIdx.x;        // o*IN_F + i
        const float* sp = sw + (size_t)idx * NB;
        float s0 = sp[0], s1 = sp[1], s2 = sp[2], s3 = sp[3], s4 = sp[4], s5 = sp[5];
        float s6 = sp[6], s7 = sp[7], s8 = sp[8], s9 = sp[9], s10 = sp[10];
        float bwv = bw[idx];
        uint4* dst = (uint4*)(g_Wh + (size_t)idx * 8);
        dst[0] = make_uint4(packh2(s0, s2), packh2(s4, s6), packh2(s8, s10), 0u);
        dst[1] = make_uint4(packh2(s1, s3), packh2(s5, s7), packh2(s9, bwv), 0u);
    } else {
        __shared__ float tile[32][33];
        int bid = blockIdx.x - PREP_WH_BLOCKS;
        int i0 = (bid % (IN_F / 32)) * 32;
        int b0 = (bid / (IN_F / 32)) * 32;
        int tx = threadIdx.x & 31, ty = threadIdx.x >> 5;  // 32x8
#pragma unroll
        for (int r = 0; r < 32; r += 8)
            tile[ty + r][tx] = x[(size_t)(b0 + ty + r) * IN_F + i0 + tx];
        __syncthreads();
#pragma unroll
        for (int r = 0; r < 32; r += 8)
            g_xT[(size_t)(i0 + ty + r) * BATCH + b0 + tx] = tile[tx][ty + r];
    }
}

// ---------------------------------------------------------------- main GEMM (one K-half)
__global__ void __launch_bounds__(THREADS, 2) kan_gemm_kernel() {
    extern __shared__ uint32_t sm[];
    const uint32_t smb = smem_u32(sm);

    const int t   = threadIdx.x;
    const int bn0 = blockIdx.x * BN;
    const int bm0 = blockIdx.y * BM;
    const int kz  = blockIdx.z;
    const int it0 = kz * NQ;

    // staging roles
    const int rloc = t & 127;             // A row this thread generates
    const int fh   = t >> 7;              // features fh*4 .. fh*4+3 of the chunk
    const int brow = t >> 1;              // B row (out column)
    const int bsel = (t & 1);             // which 128B half of the 256B row

    const float*    xbase = g_xT + bm0 + rloc;
    const uint32_t* wrow  = g_Wh + (size_t)(bn0 + brow) * (IN_F * 8);
    const uint32_t  bdst0 = smb + (BS_OFF + brow * SKB) * 4 + bsel * 128;

    // mma roles
    const int lane = t & 31, wid = t >> 5;
    const int wm0 = (wid >> 1) * 32;
    const int wn0 = (wid & 1) * 64;
    const int g  = lane >> 2, t4 = lane & 3;

    // ldmatrix per-lane addresses (A: stored/compressed tile)
    const int la7 = lane & 7, sel = lane >> 3;
    const uint32_t aAddr0 = smb +
        (((wm0 + la7 + (sel & 1) * 8) * SKA) + (sel >> 1) * 4) * 4;
    const uint32_t bAddr0 = smb + BS_OFF * 4 +
        (((wn0 + la7 + (sel >> 1) * 8) * SKB) + (sel & 1) * 4) * 4;

    // metadata: k-half split. T0 (t%4==0): k0-15 of rows (r, r+8);
    // T1 (t%4==1): k16-31 of rows (r, r+8). sh selects the 16-bit k-half.
    const int msh = (lane & 1) * 16;

    float acc[2][8][4];
#pragma unroll
    for (int mt = 0; mt < 2; mt++)
#pragma unroll
        for (int nt = 0; nt < 8; nt++)
#pragma unroll
            for (int q = 0; q < 4; q++) acc[mt][nt][q] = 0.0f;

    auto stageB = [&](int ic, int nb) {
        const char* src = (const char*)(wrow + (size_t)ic * BKF * 8) + bsel * 128;
        uint32_t dst = bdst0 + nb * (B_TB * 4);
#pragma unroll
        for (int c = 0; c < 8; c++)
            CP_ASYNC16(dst + c * 16, src + c * 16);
        CP_COMMIT();
    };

    // generate 4 features (compressed values + metadata) into buffer nb
    auto genA = [&](const float* xv, int nb) {
        uint32_t* aptr = sm + AS_OFF + nb * A_TB + rloc * SKA + fh * 16;
        uint32_t* mptr = sm + ME_OFF + nb * M_TB + rloc * 4 + fh * 2;
        uint32_t m16[4];
#pragma unroll
        for (int f = 0; f < 4; f++) {
            float xf = xv[f];
            int j0 = (int)floorf(4.0f * xf + 4.0f);
            j0 = min(7, max(0, j0));
            int p = min((j0 + (j0 & 1)) >> 1, 2);     // even-group pair (p, p+1)
            int q = min((j0 | 1) >> 1, 2);            // odd-group  pair (q, q+1)
            float s = xf / (1.0f + __expf(-xf));
            float vA0 = basis1(xf, (float)(2 * p));
            float vA1 = basis1(xf, (float)(2 * p + 2));
            float v8  = basis1(xf, 8.0f);
            float v10 = basis1(xf, 10.0f);
            float vB0 = basis1(xf, (float)(2 * q + 1));
            float vB1 = basis1(xf, (float)(2 * q + 3));
            float v9  = basis1(xf, 9.0f);
            *(uint4*)(aptr + f * 4) = make_uint4(
                packh2(vA0, vA1), packh2(v8, v10),
                packh2(vB0, vB1), packh2(v9, s));
            m16[f] = (uint32_t)((p | ((p + 1) << 2))
                   | (0x4 << 4)
                   | ((q | ((q + 1) << 2)) << 8)
                   | (0x4 << 12));
        }
        mptr[0] = m16[0] | (m16[1] << 16);
        mptr[1] = m16[2] | (m16[3] << 16);
    };

    // -------- prologue --------
    stageB(it0, 0);
    {
        float xv[4];
#pragma unroll
        for (int f = 0; f < 4; f++)
            xv[f] = xbase[(size_t)(it0 * BKF + fh * 4 + f) * BATCH];
        genA(xv, 0);
    }
    CP_WAIT0();
    __syncthreads();

    // -------- main loop --------
    for (int j = 0; j < NQ; ++j) {
        const int it = it0 + j;
        const int cur = j & 1, nxt = cur ^ 1;
        const bool hn = (j + 1 < NQ);

        float xv[4];
        if (hn) {
            stageB(it + 1, nxt);
#pragma unroll
            for (int f = 0; f < 4; f++)
                xv[f] = xbase[(size_t)((it + 1) * BKF + fh * 4 + f) * BATCH];
        }

        const uint32_t abuf = aAddr0 + (uint32_t)(cur * A_TB * 4);
        const uint32_t bbuf = bAddr0 + (uint32_t)(cur * B_TB * 4);
        const uint32_t* mp  = sm + ME_OFF + cur * M_TB;
#pragma unroll
        for (int s = 0; s < NSTEP; s++) {
            // assemble per-thread metadata: [row r k-half | row r+8 k-half]
            uint32_t wa0 = mp[(wm0 + g) * 4 + s];
            uint32_t wb0 = mp[(wm0 + g + 8) * 4 + s];
            uint32_t wa1 = mp[(wm0 + 16 + g) * 4 + s];
            uint32_t wb1 = mp[(wm0 + 16 + g + 8) * 4 + s];
            uint32_t e0 = ((wa0 >> msh) & 0xFFFFu) | (((wb0 >> msh) & 0xFFFFu) << 16);
            uint32_t e1 = ((wa1 >> msh) & 0xFFFFu) | (((wb1 >> msh) & 0xFFFFu) << 16);

            uint32_t af[2][4];
            LDSM_X4(af[0][0], af[0][1], af[0][2], af[0][3], abuf + s * 32);
            LDSM_X4(af[1][0], af[1][1], af[1][2], af[1][3],
                    abuf + s * 32 + 16 * SKA * 4);
#pragma unroll
            for (int ntp = 0; ntp < 4; ntp++) {
                uint32_t bf[2][4];
                uint32_t ba = bbuf + s * 64 + ntp * (16 * SKB * 4);
                LDSM_X4(bf[0][0], bf[0][1], bf[1][0], bf[1][1], ba);
                LDSM_X4(bf[0][2], bf[0][3], bf[1][2], bf[1][3], ba + 32);
                MMA_SP(acc[0][2 * ntp],     af[0], bf[0], e0);
                MMA_SP(acc[0][2 * ntp + 1], af[0], bf[1], e0);
                MMA_SP(acc[1][2 * ntp],     af[1], bf[0], e1);
                MMA_SP(acc[1][2 * ntp + 1], af[1], bf[1], e1);
            }
        }

        if (hn) genA(xv, nxt);

        CP_WAIT0();
        __syncthreads();
    }

    // -------- epilogue: streaming-store unclipped partials --------
    float* part = g_part + (size_t)kz * BATCH * OUT_F;
#pragma unroll
    for (int mt = 0; mt < 2; mt++) {
#pragma unroll
        for (int nt = 0; nt < 8; nt++) {
            int row = bm0 + wm0 + mt * 16 + g;
            int col = bn0 + wn0 + nt * 8 + t4 * 2;
            stcs8(&part[(size_t)row * OUT_F + col],       acc[mt][nt][0], acc[mt][nt][1]);
            stcs8(&part[(size_t)(row + 8) * OUT_F + col], acc[mt][nt][2], acc[mt][nt][3]);
        }
    }
}

// ---------------------------------------------------------------- reduce + clip
__global__ void reduce_kernel(float* __restrict__ out) {
    size_t idx = ((size_t)blockIdx.x * blockDim.x + threadIdx.x) * 4;
    const size_t S = (size_t)BATCH * OUT_F;
    const float4 p0 = ldcs16(&g_part[idx]);
    const float4 p1 = ldcs16(&g_part[S + idx]);
    float4 r;
    r.x = fminf(fmaxf(p0.x + p1.x, -1.0f), 1.0f);
    r.y = fminf(fmaxf(p0.y + p1.y, -1.0f), 1.0f);
    r.z = fminf(fmaxf(p0.z + p1.z, -1.0f), 1.0f);
    r.w = fminf(fmaxf(p0.w + p1.w, -1.0f), 1.0f);
    *(float4*)&out[idx] = r;
}

// ---------------------------------------------------------------- launch
extern "C" void kernel_launch(void* const* d_in, const int* in_sizes, int n_in,
                              void* d_out, int out_size) {
    (void)in_sizes; (void)n_in; (void)out_size;
    const float* x  = (const float*)d_in[0];
    const float* bw = (const float*)d_in[1];
    const float* sw = (const float*)d_in[2];
    float* out = (float*)d_out;

    cudaFuncSetAttribute(kan_gemm_kernel,
                         cudaFuncAttributeMaxDynamicSharedMemorySize, SMEM_BYTES);

    prep_fused_kernel<<<PREP_WH_BLOCKS + PREP_TR_BLOCKS, 256>>>(bw, sw, x);
    kan_gemm_kernel<<<dim3(OUT_F / BN, BATCH / BM, KSPLIT), THREADS, SMEM_BYTES>>>();
    reduce_kernel<<<(BATCH * OUT_F) / (256 * 4), 256>>>(out);
}